// round 1
// baseline (speedup 1.0000x reference)
#include <cuda_runtime.h>
#include <math.h>

#define BB   64
#define NN   64
#define DD   256
#define LAPD 16
#define MM   2016          // N*(N-1)/2
#define SEQ  2081          // 1 + N + M

// Scratch (no allocation allowed in kernel_launch)
__device__ float g_proju[BB * NN * DD];   // 4 MB
__device__ float g_projv[BB * NN * DD];   // 4 MB
__device__ float g_C[DD];
__device__ unsigned short g_edge[BB * MM];
__device__ int g_count[BB];

// Map linear upper-tri index m -> (i, j), i<j, row-major enumeration (triu_indices order)
__device__ __forceinline__ void m2ij(int m, int& i, int& j) {
    // off(i) = i*(127 - i)/2 for n=64
    int ii = (int)((127.0 - sqrt(16129.0 - 8.0 * (double)m)) * 0.5);
    if (ii < 0) ii = 0;
    if (ii > 62) ii = 62;
    while (ii < 62 && (ii + 1) * (127 - (ii + 1)) / 2 <= m) ii++;
    while (ii > 0 && ii * (127 - ii) / 2 > m) ii--;
    i = ii;
    j = ii + 1 + (m - ii * (127 - ii) / 2);
}

// Kernel 1: node tokens + projections + graph token + mask head + C vector
__global__ void proj_kernel(const float* __restrict__ node_feats,
                            const float* __restrict__ eigvec,
                            const float* __restrict__ W_lap,
                            const float* __restrict__ W_edge,
                            const float* __restrict__ b_edge,
                            const float* __restrict__ type_embed,
                            const float* __restrict__ graph_tok,
                            float* __restrict__ out) {
    int bid = blockIdx.x;          // b*N + n
    int b = bid >> 6;
    int n = bid & 63;
    int d = threadIdx.x;           // 0..255

    __shared__ float e[LAPD];
    if (d < LAPD) e[d] = eigvec[(size_t)bid * LAPD + d];
    __syncthreads();

    float nt = node_feats[(size_t)bid * DD + d];
    float pu = 0.f, pv = 0.f;
#pragma unroll
    for (int l = 0; l < LAPD; l++) {
        float ev = e[l];
        nt += ev * W_lap[l * DD + d];
        pu += ev * W_edge[(1 + l) * DD + d];
        pv += ev * W_edge[(1 + LAPD + l) * DD + d];
    }

    out[((size_t)b * SEQ + 1 + n) * DD + d] = nt;
    g_proju[(size_t)bid * DD + d] = pu;
    g_projv[(size_t)bid * DD + d] = pv;

    if (n == 0) {
        out[((size_t)b * SEQ) * DD + d] = graph_tok[d];
        float* maskf = out + (size_t)BB * SEQ * DD;
        if (d < 1 + NN) maskf[(size_t)b * SEQ + d] = 0.f;
        if (b == 0) g_C[d] = W_edge[d] + b_edge[d] + type_embed[DD + d];
    }
}

// Kernel 2: per-batch stable compaction of valid edges (block scan, 1024 threads, 2 elems/thread)
__global__ void scan_kernel(const int* __restrict__ adj) {
    int b = blockIdx.x;
    int t = threadIdx.x;
    __shared__ int s[1024];

    int m0 = 2 * t, m1 = 2 * t + 1;
    int v0 = 0, v1 = 0, ij0 = 0, ij1 = 0;
    if (m0 < MM) {
        int i, j; m2ij(m0, i, j);
        ij0 = (i << 6) | j;
        v0 = adj[(size_t)b * NN * NN + i * NN + j] > 0;
    }
    if (m1 < MM) {
        int i, j; m2ij(m1, i, j);
        ij1 = (i << 6) | j;
        v1 = adj[(size_t)b * NN * NN + i * NN + j] > 0;
    }
    int local = v0 + v1;
    s[t] = local;
    __syncthreads();
    for (int off = 1; off < 1024; off <<= 1) {
        int add = (t >= off) ? s[t - off] : 0;
        __syncthreads();
        s[t] += add;
        __syncthreads();
    }
    int excl = s[t] - local;
    if (v0) g_edge[b * MM + excl] = (unsigned short)ij0;
    if (v1) g_edge[b * MM + excl + v0] = (unsigned short)ij1;
    if (t == 1023) g_count[b] = s[1023];
}

// Kernel 3: edge token rows (valid: C + proju[src] + projv[dst]; else zeros) + mask tail
__global__ void edge_kernel(float* __restrict__ out) {
    int r = blockIdx.x * 4 + (threadIdx.x >> 6);   // global edge-slot row: b*M + k
    int lane = threadIdx.x & 63;                   // one float4 per lane (64*4 = 256)
    int b = r / MM;
    int k = r - b * MM;
    int K = g_count[b];

    float4 v = make_float4(0.f, 0.f, 0.f, 0.f);
    if (k < K) {
        int pack = g_edge[b * MM + k];
        int src = pack >> 6, dst = pack & 63;
        float4 a  = ((const float4*)(g_proju + (size_t)(b * NN + src) * DD))[lane];
        float4 c  = ((const float4*)(g_projv + (size_t)(b * NN + dst) * DD))[lane];
        float4 cc = ((const float4*)g_C)[lane];
        v = make_float4(a.x + c.x + cc.x, a.y + c.y + cc.y,
                        a.z + c.z + cc.z, a.w + c.w + cc.w);
    }
    ((float4*)(out + ((size_t)b * SEQ + 1 + NN + k) * DD))[lane] = v;
    if (lane == 0) {
        float* maskf = out + (size_t)BB * SEQ * DD;
        maskf[(size_t)b * SEQ + 1 + NN + k] = (k < K) ? 0.f : 1.f;
    }
}

extern "C" void kernel_launch(void* const* d_in, const int* in_sizes, int n_in,
                              void* d_out, int out_size) {
    const int*   adj        = (const int*)d_in[0];
    const float* node_feats = (const float*)d_in[1];
    const float* eigvec     = (const float*)d_in[2];
    const float* W_lap      = (const float*)d_in[3];
    const float* W_edge     = (const float*)d_in[4];
    const float* b_edge     = (const float*)d_in[5];
    const float* type_embed = (const float*)d_in[6];
    const float* graph_tok  = (const float*)d_in[7];
    float* out = (float*)d_out;

    proj_kernel<<<BB * NN, DD>>>(node_feats, eigvec, W_lap, W_edge, b_edge,
                                 type_embed, graph_tok, out);
    scan_kernel<<<BB, 1024>>>(adj);
    edge_kernel<<<(BB * MM) / 4, 256>>>(out);
}

// round 2
// speedup vs baseline: 1.8096x; 1.8096x over previous
#include <cuda_runtime.h>
#include <math.h>

#define BB   64
#define NN   64
#define DD   256
#define LAPD 16
#define MM   2016          // N*(N-1)/2
#define SEQ  2081          // 1 + N + M

// Scratch (no allocation allowed in kernel_launch)
__device__ float g_proju[BB * NN * DD];   // 4 MB  (holds proju + C folded in)
__device__ float g_projv[BB * NN * DD];   // 4 MB
__device__ unsigned short g_edge[BB * MM];
__device__ int g_count[BB];

// Map linear upper-tri index m -> (i, j), i<j, row-major (triu_indices order)
__device__ __forceinline__ void m2ij(int m, int& i, int& j) {
    int ii = (int)((127.0 - sqrt(16129.0 - 8.0 * (double)m)) * 0.5);
    if (ii < 0) ii = 0;
    if (ii > 62) ii = 62;
    while (ii < 62 && (ii + 1) * (127 - (ii + 1)) / 2 <= m) ii++;
    while (ii > 0 && ii * (127 - ii) / 2 > m) ii--;
    i = ii;
    j = ii + 1 + (m - ii * (127 - ii) / 2);
}

// Fused kernel: blocks [0,256) = proj (b = blk>>2, node group = blk&3, 16 nodes each),
//               blocks [256,320) = per-batch stable compaction scan.
__global__ void fused_proj_scan(const float* __restrict__ node_feats,
                                const float* __restrict__ eigvec,
                                const float* __restrict__ W_lap,
                                const float* __restrict__ W_edge,
                                const float* __restrict__ b_edge,
                                const float* __restrict__ type_embed,
                                const float* __restrict__ graph_tok,
                                const int*  __restrict__ adj,
                                float* __restrict__ out) {
    __shared__ float sh[256];   // proj: eigvec tile; scan: reused as int scan buffer
    int tid = threadIdx.x;

    if (blockIdx.x < 256) {
        // ---------------- proj part ----------------
        int b  = blockIdx.x >> 2;
        int g  = blockIdx.x & 3;
        int n0 = g * 16;
        int d  = tid;

        // W held in registers (fixed d per thread)
        float wl[LAPD], wu[LAPD], wv[LAPD];
#pragma unroll
        for (int l = 0; l < LAPD; l++) {
            wl[l] = __ldg(&W_lap[l * DD + d]);
            wu[l] = __ldg(&W_edge[(1 + l) * DD + d]);
            wv[l] = __ldg(&W_edge[(1 + LAPD + l) * DD + d]);
        }
        float Cd = __ldg(&W_edge[d]) + __ldg(&b_edge[d]) + __ldg(&type_embed[DD + d]);

        // 16 nodes x 16 lap coeffs into smem
        sh[tid] = eigvec[(size_t)(b * NN + n0) * LAPD + tid];
        __syncthreads();

#pragma unroll 4
        for (int n = 0; n < 16; n++) {
            int node = b * NN + n0 + n;
            float nt = node_feats[(size_t)node * DD + d];
            float pu = 0.f, pv = 0.f;
#pragma unroll
            for (int l = 0; l < LAPD; l++) {
                float ev = sh[n * LAPD + l];
                nt += ev * wl[l];
                pu += ev * wu[l];
                pv += ev * wv[l];
            }
            __stcs(&out[((size_t)b * SEQ + 1 + n0 + n) * DD + d], nt);
            g_proju[(size_t)node * DD + d] = pu + Cd;
            g_projv[(size_t)node * DD + d] = pv;
        }

        if (g == 0) {
            __stcs(&out[(size_t)b * SEQ * DD + d], graph_tok[d]);
            float* maskf = out + (size_t)BB * SEQ * DD;
            if (d < 1 + NN) maskf[(size_t)b * SEQ + d] = 0.f;
        }
    } else {
        // ---------------- scan part ----------------
        int b = blockIdx.x - 256;
        int* s = (int*)sh;
        const int* adjb = adj + (size_t)b * NN * NN;

        // each thread handles 8 consecutive m
        int m0 = tid * 8;
        int i, j;
        int v[8], ij[8];
        int local = 0;
        if (m0 < MM) {
            m2ij(m0, i, j);
#pragma unroll
            for (int q = 0; q < 8; q++) {
                int m = m0 + q;
                int val = 0, pack = 0;
                if (m < MM) {
                    pack = (i << 6) | j;
                    val = adjb[i * NN + j] > 0;
                    // advance (i,j)
                    j++;
                    if (j == NN) { i++; j = i + 1; }
                }
                v[q] = val; ij[q] = pack;
                local += val;
            }
        } else {
#pragma unroll
            for (int q = 0; q < 8; q++) { v[q] = 0; ij[q] = 0; }
        }

        s[tid] = local;
        __syncthreads();
#pragma unroll
        for (int off = 1; off < 256; off <<= 1) {
            int add = (tid >= off) ? s[tid - off] : 0;
            __syncthreads();
            s[tid] += add;
            __syncthreads();
        }
        int pos = s[tid] - local;
#pragma unroll
        for (int q = 0; q < 8; q++) {
            if (v[q]) g_edge[b * MM + pos++] = (unsigned short)ij[q];
        }
        if (tid == 255) g_count[b] = s[255];
    }
}

// Edge kernel: 8 rows/block (2 per 64-lane group for ILP), float4 streaming stores.
// 2016 / 8 = 252 blocks per batch -> no block straddles a batch.
__global__ void edge_kernel(float* __restrict__ out) {
    int b     = blockIdx.x / 252;
    int local = blockIdx.x - b * 252;
    int rg    = threadIdx.x >> 6;
    int lane  = threadIdx.x & 63;
    int kA = local * 8 + rg;
    int kB = kA + 4;
    int K = g_count[b];

    float4 vA = make_float4(0.f, 0.f, 0.f, 0.f);
    float4 vB = vA;

    int pA = (kA < K) ? (int)g_edge[b * MM + kA] : -1;
    int pB = (kB < K) ? (int)g_edge[b * MM + kB] : -1;

    if (pA >= 0) {
        float4 a = __ldg(&((const float4*)(g_proju + (size_t)(b * NN + (pA >> 6)) * DD))[lane]);
        float4 c = __ldg(&((const float4*)(g_projv + (size_t)(b * NN + (pA & 63)) * DD))[lane]);
        vA = make_float4(a.x + c.x, a.y + c.y, a.z + c.z, a.w + c.w);
    }
    if (pB >= 0) {
        float4 a = __ldg(&((const float4*)(g_proju + (size_t)(b * NN + (pB >> 6)) * DD))[lane]);
        float4 c = __ldg(&((const float4*)(g_projv + (size_t)(b * NN + (pB & 63)) * DD))[lane]);
        vB = make_float4(a.x + c.x, a.y + c.y, a.z + c.z, a.w + c.w);
    }

    __stcs(&((float4*)(out + ((size_t)b * SEQ + 1 + NN + kA) * DD))[lane], vA);
    __stcs(&((float4*)(out + ((size_t)b * SEQ + 1 + NN + kB) * DD))[lane], vB);

    if (lane == 0) {
        float* maskf = out + (size_t)BB * SEQ * DD;
        maskf[(size_t)b * SEQ + 1 + NN + kA] = (kA < K) ? 0.f : 1.f;
        maskf[(size_t)b * SEQ + 1 + NN + kB] = (kB < K) ? 0.f : 1.f;
    }
}

extern "C" void kernel_launch(void* const* d_in, const int* in_sizes, int n_in,
                              void* d_out, int out_size) {
    const int*   adj        = (const int*)d_in[0];
    const float* node_feats = (const float*)d_in[1];
    const float* eigvec     = (const float*)d_in[2];
    const float* W_lap      = (const float*)d_in[3];
    const float* W_edge     = (const float*)d_in[4];
    const float* b_edge     = (const float*)d_in[5];
    const float* type_embed = (const float*)d_in[6];
    const float* graph_tok  = (const float*)d_in[7];
    float* out = (float*)d_out;

    fused_proj_scan<<<320, 256>>>(node_feats, eigvec, W_lap, W_edge, b_edge,
                                  type_embed, graph_tok, adj, out);
    edge_kernel<<<BB * 252, 256>>>(out);
}